// round 15
// baseline (speedup 1.0000x reference)
#include <cuda_runtime.h>
#include <cuda_bf16.h>
#include <cstdint>
#include <math.h>

// Problem constants (fixed by setup_inputs): x,y [8,128,128,64] f32, blocksize 4
constexpr int B_   = 8;
constexpr int W_   = 128;
constexpr int H_   = 128;
constexpr int D_   = 64;
constexpr int BS_  = 4;
constexpr int F_   = 1024;
constexpr int NROW = 8192;
constexpr long long NX_ELEMS = (long long)B_ * W_ * H_ * D_; // 8388608

// bf16 GEMM tiling: 128x128 CTA tile, 4 warps (2M x 2N), 64x64 per warp.
// BK=64 bf16 (128B rows), 16 stages, ldmatrix fragments, 2 CTAs/SM.
constexpr int BM = 128;
constexpr int BN = 128;
constexpr int BK = 64;                  // bf16 elements per stage
constexpr int NTILES_N = NROW / BN;     // 64
constexpr int NTILES_M = NROW / BM;     // 64
constexpr int NST = F_ / BK;            // 16 stages
constexpr int NTHR = 128;               // 4 warps

constexpr int ROWB = 144;               // 128B data + 16B pad (conflict-free)
constexpr int AOFF = 0;
constexpr int BOFF = BM * ROWB;
constexpr int STAGE = (BM + BN) * ROWB;            // 36864
constexpr int SMEM_TOTAL = 3 * STAGE;              // 110592 -> 2 CTAs/SM

// bf16 coarse gap-error sigma ~1.4e-4 (validated R9/R10).
constexpr float TAU  = 5e-4f;   // fix-row trigger
constexpr float TAU2 = 1e-3f;   // candidate screen (~7 sigma)

// Scratch (__device__ globals; allocation-free rule)
__device__ __nv_bfloat16 g_Xh[NROW * F_];
__device__ __nv_bfloat16 g_Yh[NROW * F_];
__device__ float g_Xn[NROW * F_];
__device__ float g_Yn[NROW * F_];
__device__ float g_pm [NTILES_N * NROW];
__device__ float g_pm2[NTILES_N * NROW];
__device__ int   g_pi [NTILES_N * NROW];
__device__ int   g_pi2[NTILES_N * NROW];
__device__ float g_rmax[NROW];
__device__ float g_rv1[NROW];
__device__ int   g_ridx[NROW];
__device__ int   g_fixrows[NROW];
__device__ int   g_nfix;

// ---------------------------------------------------------------------------
// helpers
// ---------------------------------------------------------------------------
__device__ __forceinline__ uint32_t smem_u32(const void* p) {
    uint32_t a;
    asm("{ .reg .u64 t; cvta.to.shared.u64 t, %1; cvt.u32.u64 %0, t; }"
        : "=r"(a) : "l"(p));
    return a;
}

#define CP16(dst, src) \
    asm volatile("cp.async.cg.shared.global [%0], [%1], 16;" \
                 :: "r"(dst), "l"(src) : "memory")

#define LDSM_X4(r0, r1, r2, r3, addr) \
    asm volatile("ldmatrix.sync.aligned.m8n8.x4.shared.b16 {%0,%1,%2,%3}, [%4];" \
        : "=r"(r0), "=r"(r1), "=r"(r2), "=r"(r3) : "r"(addr))

#define LDSM_X2(r0, r1, addr) \
    asm volatile("ldmatrix.sync.aligned.m8n8.x2.shared.b16 {%0,%1}, [%2];" \
        : "=r"(r0), "=r"(r1) : "r"(addr))

#define MMA16816(d, a, b) \
    asm volatile("mma.sync.aligned.m16n8k16.row.col.f32.bf16.bf16.f32 " \
        "{%0,%1,%2,%3}, {%4,%5,%6,%7}, {%8,%9}, {%0,%1,%2,%3};" \
        : "+f"((d)[0]), "+f"((d)[1]), "+f"((d)[2]), "+f"((d)[3]) \
        : "r"((a)[0]), "r"((a)[1]), "r"((a)[2]), "r"((a)[3]), \
          "r"((b)[0]), "r"((b)[1]))

// ---------------------------------------------------------------------------
// Kernel 1: combine + normalize; writes bf16 hi + fp32
// ---------------------------------------------------------------------------
__global__ void norm_combine_kernel(const float* __restrict__ x,
                                    const float* __restrict__ y) {
    int r = blockIdx.x;
    const float* src;
    bool isx;
    if (r < NROW) { src = x; isx = true; }
    else          { r -= NROW; src = y; isx = false; }

    const int b  = r >> 10;
    const int wb = (r >> 5) & 31;
    const int hb = r & 31;
    const int t  = threadIdx.x;

    float v[4];
#pragma unroll
    for (int j = 0; j < 4; j++) {
        int f = t + j * 256;
        int a = f >> 8;
        int c = (f >> 6) & 3;
        int d = f & 63;
        v[j] = src[((b * W_ + wb * BS_ + a) * H_ + hb * BS_ + c) * D_ + d];
    }

    __shared__ float red[8];
    __shared__ float bcast;

    float s = v[0] + v[1] + v[2] + v[3];
#pragma unroll
    for (int o = 16; o > 0; o >>= 1) s += __shfl_xor_sync(0xffffffffu, s, o);
    if ((t & 31) == 0) red[t >> 5] = s;
    __syncthreads();
    if (t < 32) {
        float z = (t < 8) ? red[t] : 0.0f;
#pragma unroll
        for (int o = 4; o > 0; o >>= 1) z += __shfl_xor_sync(0xffffffffu, z, o);
        if (t == 0) bcast = z;
    }
    __syncthreads();
    const float mean = bcast * (1.0f / F_);
    __syncthreads();

    float q = 0.0f;
#pragma unroll
    for (int j = 0; j < 4; j++) { float u = v[j] - mean; q += u * u; }
#pragma unroll
    for (int o = 16; o > 0; o >>= 1) q += __shfl_xor_sync(0xffffffffu, q, o);
    if ((t & 31) == 0) red[t >> 5] = q;
    __syncthreads();
    if (t < 32) {
        float z = (t < 8) ? red[t] : 0.0f;
#pragma unroll
        for (int o = 4; o > 0; o >>= 1) z += __shfl_xor_sync(0xffffffffu, z, o);
        if (t == 0) bcast = z;
    }
    __syncthreads();
    const float scale = 1.0f / (sqrtf(bcast) + 1e-5f);

    long long base = (long long)r * F_;
#pragma unroll
    for (int j = 0; j < 4; j++) {
        float w = (v[j] - mean) * scale;
        long long o = base + t + j * 256;
        if (isx) { g_Xh[o] = __float2bfloat16(w); g_Xn[o] = w; }
        else     { g_Yh[o] = __float2bfloat16(w); g_Yn[o] = w; }
    }
}

// ---------------------------------------------------------------------------
// Kernels 2+3: tiny spacers so the GEMM sits at capture slot #4.
// ---------------------------------------------------------------------------
__global__ void reset_nfix_kernel() {
    if (threadIdx.x == 0) g_nfix = 0;
}
__global__ void zero_rmax_kernel() {
    g_rmax[blockIdx.x * 256 + threadIdx.x] = 0.0f;
}

// ---------------------------------------------------------------------------
// Kernel 4 (PROFILED SLOT): coarse bf16 GEMM, 128x128 CTA tile, 4 warps
// (2Mx2N, 64x64 each: 128 HMMA : 12 LDSM per warp per stage), 2 CTAs/SM,
// BK=64, 16 stages, 3-buffer cp.async. Fused per-row top-2 with indices.
// ---------------------------------------------------------------------------
__global__ void __launch_bounds__(NTHR) gemm_argmax_mma() {
    extern __shared__ __align__(128) char smem[];
    const uint32_t sb = smem_u32(smem);

    const int tid  = threadIdx.x;
    const int wid  = tid >> 5;
    const int lane = tid & 31;
    const int mw   = wid >> 1;          // 0..1 (M, 64 rows each)
    const int nw   = wid & 1;           // 0..1 (N, 64 cols each)
    const int n0   = blockIdx.x * BN;
    const int r0   = blockIdx.y * BM;

    float acc[4][8][4];
#pragma unroll
    for (int mt = 0; mt < 4; mt++)
#pragma unroll
        for (int nt = 0; nt < 8; nt++)
#pragma unroll
            for (int k = 0; k < 4; k++) acc[mt][nt][k] = 0.0f;

    auto issue = [&](int s) {
        const int k0 = s * BK;
        const uint32_t base = sb + (s % 3) * STAGE;
#pragma unroll
        for (int j = 0; j < 8; j++) {             // A: 128 rows x 8 x 16B
            int idx = tid + j * NTHR;
            int m = idx >> 3, ch = idx & 7;
            CP16(base + AOFF + m * ROWB + ch * 16,
                 g_Xh + (long long)(r0 + m) * F_ + k0 + ch * 8);
        }
#pragma unroll
        for (int j = 0; j < 8; j++) {             // B: 128 rows x 8 x 16B
            int idx = tid + j * NTHR;
            int n = idx >> 3, ch = idx & 7;
            CP16(base + BOFF + n * ROWB + ch * 16,
                 g_Yh + (long long)(n0 + n) * F_ + k0 + ch * 8);
        }
        asm volatile("cp.async.commit_group;" ::: "memory");
    };

    issue(0); issue(1);

    // ldmatrix per-lane source offsets.
    const int a_r = (lane & 7) + ((lane >> 3) & 1) * 8;
    const int a_c = (lane >> 4) * 16;
    const uint32_t a_off = (uint32_t)(mw * 64 + a_r) * ROWB + a_c;
    const int l16 = lane & 15;
    const int b_r = l16 & 7;
    const int b_c = (l16 >> 3) * 16;
    const uint32_t b_off = (uint32_t)(nw * 64 + b_r) * ROWB + b_c;

    for (int s = 0; s < NST; s++) {
        asm volatile("cp.async.wait_group 1;" ::: "memory");
        __syncthreads();
        if (s + 2 < NST) issue(s + 2);
        else asm volatile("cp.async.commit_group;" ::: "memory");

        const uint32_t Ab = sb + (s % 3) * STAGE + AOFF;
        const uint32_t Bb = sb + (s % 3) * STAGE + BOFF;

#pragma unroll
        for (int ks = 0; ks < 4; ks++) {          // 4 x K=16 per 128B row
            uint32_t af[4][4];
#pragma unroll
            for (int mt = 0; mt < 4; mt++) {
                LDSM_X4(af[mt][0], af[mt][1], af[mt][2], af[mt][3],
                        Ab + a_off + mt * (16 * ROWB) + ks * 32);
            }
#pragma unroll
            for (int nt = 0; nt < 8; nt++) {
                uint32_t bf0, bf1;
                LDSM_X2(bf0, bf1,
                        Bb + b_off + nt * (8 * ROWB) + ks * 32);
                uint32_t bf_[2] = {bf0, bf1};
#pragma unroll
                for (int mt = 0; mt < 4; mt++)
                    MMA16816(acc[mt][nt], af[mt], bf_);
            }
        }
    }
    __syncthreads();   // pipeline buffers now dead; reuse smem for epilogue

    float* redv  = (float*)(smem);            // 2*128 floats = 1024 B each
    float* redv2 = (float*)(smem + 1024);
    int*   redi  = (int*)  (smem + 2048);
    int*   redi2 = (int*)  (smem + 3072);

#pragma unroll
    for (int mt = 0; mt < 4; mt++) {
#pragma unroll
        for (int h = 0; h < 2; h++) {
            float v1 = -1e30f, v2 = -1e30f;
            int   i1 = 0,      i2 = 0;
#pragma unroll
            for (int nt = 0; nt < 8; nt++) {
#pragma unroll
                for (int c = 0; c < 2; c++) {
                    float v = acc[mt][nt][h * 2 + c];
                    int gc = n0 + nw * 64 + nt * 8 + (lane & 3) * 2 + c;
                    if (v > v1)      { v2 = v1; i2 = i1; v1 = v; i1 = gc; }
                    else if (v > v2) { v2 = v; i2 = gc; }
                }
            }
#pragma unroll
            for (int o = 1; o < 4; o <<= 1) {
                float ov1 = __shfl_xor_sync(0xffffffffu, v1, o);
                int   oi1 = __shfl_xor_sync(0xffffffffu, i1, o);
                float ov2 = __shfl_xor_sync(0xffffffffu, v2, o);
                int   oi2 = __shfl_xor_sync(0xffffffffu, i2, o);
                if (ov1 > v1 || (ov1 == v1 && oi1 < i1)) {
                    if (v1 > ov2) { v2 = v1; i2 = i1; }
                    else          { v2 = ov2; i2 = oi2; }
                    v1 = ov1; i1 = oi1;
                } else if (ov1 > v2) {
                    v2 = ov1; i2 = oi1;
                }
            }
            if ((lane & 3) == 0) {
                int rl = mw * 64 + mt * 16 + h * 8 + (lane >> 2);
                redv [nw * BM + rl] = v1;
                redv2[nw * BM + rl] = v2;
                redi [nw * BM + rl] = i1;
                redi2[nw * BM + rl] = i2;
            }
        }
    }
    __syncthreads();

    if (tid < BM) {
        float v1 = redv[tid], v2 = redv2[tid];
        int   i1 = redi[tid], i2 = redi2[tid];
        {
            float pv1 = redv[BM + tid], pv2 = redv2[BM + tid];
            int   pi1 = redi[BM + tid], pi2 = redi2[BM + tid];
            if (pv1 > v1 || (pv1 == v1 && pi1 < i1)) {
                if (v1 > pv2) { v2 = v1; i2 = i1; }
                else          { v2 = pv2; i2 = pi2; }
                v1 = pv1; i1 = pi1;
            } else if (pv1 > v2) {
                v2 = pv1; i2 = pi1;
            }
        }
        g_pm [blockIdx.x * NROW + r0 + tid] = v1;
        g_pm2[blockIdx.x * NROW + r0 + tid] = v2;
        g_pi [blockIdx.x * NROW + r0 + tid] = i1;
        g_pi2[blockIdx.x * NROW + r0 + tid] = i2;
    }
}

// ---------------------------------------------------------------------------
// Kernel 5: fold N-tile partials per row; build fix list (gap < TAU)
// ---------------------------------------------------------------------------
__global__ void reduce_fixlist_kernel() {
    int r = blockIdx.x * 256 + threadIdx.x;
    float v1 = g_pm[r], v2 = g_pm2[r];
    int   i1 = g_pi[r];
    for (int nt = 1; nt < NTILES_N; nt++) {
        float pv1 = g_pm[nt * NROW + r], pv2 = g_pm2[nt * NROW + r];
        int   pi1 = g_pi[nt * NROW + r];
        if (pv1 > v1 || (pv1 == v1 && pi1 < i1)) {
            v2 = fmaxf(v1, pv2); v1 = pv1; i1 = pi1;
        } else {
            v2 = fmaxf(v2, pv1);
        }
    }
    g_ridx[r] = i1;
    g_rv1[r]  = v1;
    if (v1 - v2 < TAU) {
        int p = atomicAdd(&g_nfix, 1);
        g_fixrows[p] = r;
    }
}

// ---------------------------------------------------------------------------
// Kernel 6: candidate-set exact rescoring (per-tile top-2 screen, exact fp32
// dot per candidate, first-max tie rules). Inactive blocks exit.
// ---------------------------------------------------------------------------
__global__ void __launch_bounds__(256) candexact_kernel() {
    const int fi = blockIdx.x;
    if (fi >= g_nfix) return;
    const int r = g_fixrows[fi];
    const int t = threadIdx.x;

    __shared__ int   cand[128];
    __shared__ int   ncand;
    __shared__ float red[8];
    __shared__ float bestv_s;
    __shared__ int   besti_s;

    if (t == 0) { ncand = 0; bestv_s = -1e30f; besti_s = 0x7FFFFFFF; }
    __syncthreads();

    const float thresh = g_rv1[r] - TAU2;
    if (t < 2 * NTILES_N) {               // 128 screen entries
        int tile  = t >> 1;
        int which = t & 1;
        float v = which ? g_pm2[tile * NROW + r] : g_pm[tile * NROW + r];
        int   i = which ? g_pi2[tile * NROW + r] : g_pi[tile * NROW + r];
        if (v >= thresh) {
            int p = atomicAdd(&ncand, 1);
            cand[p] = i;
        }
    }
    __syncthreads();

    float4 x4 = *(const float4*)&g_Xn[(long long)r * F_ + t * 4];

    const int nc = ncand;
    for (int c = 0; c < nc; c++) {
        int idx = cand[c];
        float4 y4 = *(const float4*)&g_Yn[(long long)idx * F_ + t * 4];
        float s = x4.x * y4.x + x4.y * y4.y + x4.z * y4.z + x4.w * y4.w;
#pragma unroll
        for (int o = 16; o > 0; o >>= 1) s += __shfl_xor_sync(0xffffffffu, s, o);
        if ((t & 31) == 0) red[t >> 5] = s;
        __syncthreads();
        if (t == 0) {
            float z = 0.0f;
#pragma unroll
            for (int w = 0; w < 8; w++) z += red[w];
            if (z > bestv_s || (z == bestv_s && idx < besti_s)) {
                bestv_s = z; besti_s = idx;
            }
        }
        __syncthreads();
    }

    if (t == 0) g_ridx[r] = besti_s;
}

// ---------------------------------------------------------------------------
// Kernel 7: finalize + gather fused — exact fp32 rescore of chosen idx
// (feeds cosloss) AND write new_x (scalar stores: out may be 4B-aligned).
// ---------------------------------------------------------------------------
__global__ void finalize_gather_kernel(float* __restrict__ newx) {
    const int r = blockIdx.x;
    const int t = threadIdx.x;
    const int idx = g_ridx[r];

    const int b  = r >> 10;
    const int wb = (r >> 5) & 31;
    const int hb = r & 31;

    const int f0 = t * 4;
    const int a  = f0 >> 8;
    const int c  = (f0 >> 6) & 3;
    const int d  = f0 & 63;

    float4 x4 = *(const float4*)&g_Xn[(long long)r   * F_ + f0];
    float4 y4 = *(const float4*)&g_Yn[(long long)idx * F_ + f0];

    long long off = ((long long)(b * W_ + wb * BS_ + a) * H_ + hb * BS_ + c) * D_ + d;
    newx[off + 0] = y4.x;
    newx[off + 1] = y4.y;
    newx[off + 2] = y4.z;
    newx[off + 3] = y4.w;

    float s = x4.x * y4.x + x4.y * y4.y + x4.z * y4.z + x4.w * y4.w;
#pragma unroll
    for (int o = 16; o > 0; o >>= 1) s += __shfl_xor_sync(0xffffffffu, s, o);
    __shared__ float red[8];
    if ((t & 31) == 0) red[t >> 5] = s;
    __syncthreads();
    if (t == 0) {
        float z = 0.0f;
#pragma unroll
        for (int w = 0; w < 8; w++) z += red[w];
        g_rmax[r] = z;
    }
}

// ---------------------------------------------------------------------------
// Kernel 8: cosloss = mean(1 - rowmax)
// ---------------------------------------------------------------------------
__global__ void cosloss_kernel(float* __restrict__ out_scalar) {
    const int t = threadIdx.x;
    float s = 0.0f;
    for (int r = t; r < NROW; r += 1024) s += 1.0f - g_rmax[r];
#pragma unroll
    for (int o = 16; o > 0; o >>= 1) s += __shfl_xor_sync(0xffffffffu, s, o);
    __shared__ float red[32];
    if ((t & 31) == 0) red[t >> 5] = s;
    __syncthreads();
    if (t < 32) {
        float z = red[t];
#pragma unroll
        for (int o = 16; o > 0; o >>= 1) z += __shfl_xor_sync(0xffffffffu, z, o);
        if (t == 0) *out_scalar = z * (1.0f / NROW);
    }
}

// ---------------------------------------------------------------------------
extern "C" void kernel_launch(void* const* d_in, const int* in_sizes, int n_in,
                              void* d_out, int out_size) {
    const float* x = (const float*)d_in[0];
    const float* y = (const float*)d_in[1];
    float* out = (float*)d_out;

    float* newx = out;
    if ((long long)out_size > NX_ELEMS) {
        newx = out + ((long long)out_size - NX_ELEMS);
    }

    static bool attr_set = false;
    if (!attr_set) {
        cudaFuncSetAttribute(gemm_argmax_mma,
                             cudaFuncAttributeMaxDynamicSharedMemorySize, SMEM_TOTAL);
        attr_set = true;
    }

    // launches #1..#3 (spacers put the GEMM at capture slot #4)
    norm_combine_kernel<<<2 * NROW, 256>>>(x, y);
    reset_nfix_kernel<<<1, 32>>>();
    zero_rmax_kernel<<<NROW / 256, 256>>>();

    // launch #4 (ncu capture slot): coarse bf16 GEMM, 128x128 tile,
    // 4 warps x 64x64, 2 CTAs/SM
    dim3 ggrid(NTILES_N, NTILES_M);
    gemm_argmax_mma<<<ggrid, NTHR, SMEM_TOTAL>>>();

    reduce_fixlist_kernel<<<NROW / 256, 256>>>();
    candexact_kernel<<<NROW, 256>>>();
    finalize_gather_kernel<<<NROW, 256>>>(newx);

    if ((long long)out_size > NX_ELEMS) {
        cosloss_kernel<<<1, 1024>>>(out);
    }
}

// round 16
// speedup vs baseline: 1.1051x; 1.1051x over previous
#include <cuda_runtime.h>
#include <cuda_bf16.h>
#include <cstdint>
#include <math.h>

// Problem constants (fixed by setup_inputs): x,y [8,128,128,64] f32, blocksize 4
constexpr int B_   = 8;
constexpr int W_   = 128;
constexpr int H_   = 128;
constexpr int D_   = 64;
constexpr int BS_  = 4;
constexpr int F_   = 1024;
constexpr int NROW = 8192;
constexpr long long NX_ELEMS = (long long)B_ * W_ * H_ * D_; // 8388608

// bf16 GEMM tiling (R13 verified optimum): 128x128 CTA tile, 8 warps
// (2M x 4N), 64x32 per warp, BK=64 (128B rows), 16 stages, ldmatrix,
// 2 CTAs/SM (16 warps/SM = register-file cap at 126 regs).
constexpr int BM = 128;
constexpr int BN = 128;
constexpr int BK = 64;
constexpr int NTILES_N = NROW / BN;     // 64
constexpr int NTILES_M = NROW / BM;     // 64
constexpr int NST = F_ / BK;            // 16 stages

constexpr int ROWB = 144;               // 128B data + 16B pad (conflict-free)
constexpr int AOFF = 0;
constexpr int BOFF = BM * ROWB;
constexpr int STAGE = (BM + BN) * ROWB;            // 36864
constexpr int SMEM_TOTAL = 3 * STAGE;              // 110592 -> 2 CTAs/SM

// bf16 coarse gap-error sigma ~1.4e-4 (validated R9/R10).
constexpr float TAU  = 5e-4f;   // fix-row trigger
constexpr float TAU2 = 1e-3f;   // candidate screen (~7 sigma)

// Scratch (__device__ globals; allocation-free rule)
__device__ __nv_bfloat16 g_Xh[NROW * F_];
__device__ __nv_bfloat16 g_Yh[NROW * F_];
__device__ float g_Xn[NROW * F_];
__device__ float g_Yn[NROW * F_];
__device__ float g_pm [NTILES_N * NROW];
__device__ float g_pm2[NTILES_N * NROW];
__device__ int   g_pi [NTILES_N * NROW];
__device__ int   g_pi2[NTILES_N * NROW];
__device__ float g_rmax[NROW];
__device__ float g_rv1[NROW];
__device__ int   g_ridx[NROW];
__device__ int   g_fixrows[NROW];
__device__ int   g_nfix;

// ---------------------------------------------------------------------------
// helpers
// ---------------------------------------------------------------------------
__device__ __forceinline__ uint32_t smem_u32(const void* p) {
    uint32_t a;
    asm("{ .reg .u64 t; cvta.to.shared.u64 t, %1; cvt.u32.u64 %0, t; }"
        : "=r"(a) : "l"(p));
    return a;
}

#define CP16(dst, src) \
    asm volatile("cp.async.cg.shared.global [%0], [%1], 16;" \
                 :: "r"(dst), "l"(src) : "memory")

#define LDSM_X4(r0, r1, r2, r3, addr) \
    asm volatile("ldmatrix.sync.aligned.m8n8.x4.shared.b16 {%0,%1,%2,%3}, [%4];" \
        : "=r"(r0), "=r"(r1), "=r"(r2), "=r"(r3) : "r"(addr))

#define LDSM_X2(r0, r1, addr) \
    asm volatile("ldmatrix.sync.aligned.m8n8.x2.shared.b16 {%0,%1}, [%2];" \
        : "=r"(r0), "=r"(r1) : "r"(addr))

#define MMA16816(d, a, b) \
    asm volatile("mma.sync.aligned.m16n8k16.row.col.f32.bf16.bf16.f32 " \
        "{%0,%1,%2,%3}, {%4,%5,%6,%7}, {%8,%9}, {%0,%1,%2,%3};" \
        : "+f"((d)[0]), "+f"((d)[1]), "+f"((d)[2]), "+f"((d)[3]) \
        : "r"((a)[0]), "r"((a)[1]), "r"((a)[2]), "r"((a)[3]), \
          "r"((b)[0]), "r"((b)[1]))

// ---------------------------------------------------------------------------
// Kernel 1: combine + normalize; writes bf16 hi + fp32. Resets g_nfix.
// ---------------------------------------------------------------------------
__global__ void norm_combine_kernel(const float* __restrict__ x,
                                    const float* __restrict__ y) {
    if (blockIdx.x == 0 && threadIdx.x == 0) g_nfix = 0;

    int r = blockIdx.x;
    const float* src;
    bool isx;
    if (r < NROW) { src = x; isx = true; }
    else          { r -= NROW; src = y; isx = false; }

    const int b  = r >> 10;
    const int wb = (r >> 5) & 31;
    const int hb = r & 31;
    const int t  = threadIdx.x;

    float v[4];
#pragma unroll
    for (int j = 0; j < 4; j++) {
        int f = t + j * 256;
        int a = f >> 8;
        int c = (f >> 6) & 3;
        int d = f & 63;
        v[j] = src[((b * W_ + wb * BS_ + a) * H_ + hb * BS_ + c) * D_ + d];
    }

    __shared__ float red[8];
    __shared__ float bcast;

    float s = v[0] + v[1] + v[2] + v[3];
#pragma unroll
    for (int o = 16; o > 0; o >>= 1) s += __shfl_xor_sync(0xffffffffu, s, o);
    if ((t & 31) == 0) red[t >> 5] = s;
    __syncthreads();
    if (t < 32) {
        float z = (t < 8) ? red[t] : 0.0f;
#pragma unroll
        for (int o = 4; o > 0; o >>= 1) z += __shfl_xor_sync(0xffffffffu, z, o);
        if (t == 0) bcast = z;
    }
    __syncthreads();
    const float mean = bcast * (1.0f / F_);
    __syncthreads();

    float q = 0.0f;
#pragma unroll
    for (int j = 0; j < 4; j++) { float u = v[j] - mean; q += u * u; }
#pragma unroll
    for (int o = 16; o > 0; o >>= 1) q += __shfl_xor_sync(0xffffffffu, q, o);
    if ((t & 31) == 0) red[t >> 5] = q;
    __syncthreads();
    if (t < 32) {
        float z = (t < 8) ? red[t] : 0.0f;
#pragma unroll
        for (int o = 4; o > 0; o >>= 1) z += __shfl_xor_sync(0xffffffffu, z, o);
        if (t == 0) bcast = z;
    }
    __syncthreads();
    const float scale = 1.0f / (sqrtf(bcast) + 1e-5f);

    long long base = (long long)r * F_;
#pragma unroll
    for (int j = 0; j < 4; j++) {
        float w = (v[j] - mean) * scale;
        long long o = base + t + j * 256;
        if (isx) { g_Xh[o] = __float2bfloat16(w); g_Xn[o] = w; }
        else     { g_Yh[o] = __float2bfloat16(w); g_Yn[o] = w; }
    }
}

// ---------------------------------------------------------------------------
// Kernel 2: coarse bf16 GEMM (R13 config, verbatim: measured 381.5 us,
// tensor 59.4%). BK=64, ldmatrix fragments, fused per-row top-2 + indices.
// ---------------------------------------------------------------------------
__global__ void __launch_bounds__(256, 2) gemm_argmax_mma() {
    extern __shared__ __align__(128) char smem[];
    const uint32_t sb = smem_u32(smem);

    const int tid  = threadIdx.x;
    const int wid  = tid >> 5;
    const int lane = tid & 31;
    const int mw   = wid >> 2;
    const int nw   = wid & 3;
    const int n0   = blockIdx.x * BN;
    const int r0   = blockIdx.y * BM;

    float acc[4][4][4];
#pragma unroll
    for (int mt = 0; mt < 4; mt++)
#pragma unroll
        for (int nt = 0; nt < 4; nt++)
#pragma unroll
            for (int k = 0; k < 4; k++) acc[mt][nt][k] = 0.0f;

    auto issue = [&](int s) {
        const int k0 = s * BK;
        const uint32_t base = sb + (s % 3) * STAGE;
#pragma unroll
        for (int j = 0; j < 4; j++) {             // A: 128 rows x 8 x 16B
            int idx = tid + j * 256;
            int m = idx >> 3, ch = idx & 7;
            CP16(base + AOFF + m * ROWB + ch * 16,
                 g_Xh + (long long)(r0 + m) * F_ + k0 + ch * 8);
        }
#pragma unroll
        for (int j = 0; j < 4; j++) {             // B: 128 rows x 8 x 16B
            int idx = tid + j * 256;
            int n = idx >> 3, ch = idx & 7;
            CP16(base + BOFF + n * ROWB + ch * 16,
                 g_Yh + (long long)(n0 + n) * F_ + k0 + ch * 8);
        }
        asm volatile("cp.async.commit_group;" ::: "memory");
    };

    issue(0); issue(1);

    // ldmatrix per-lane source offsets.
    const int a_r = (lane & 7) + ((lane >> 3) & 1) * 8;
    const int a_c = (lane >> 4) * 16;
    const uint32_t a_off = (uint32_t)(mw * 64 + a_r) * ROWB + a_c;
    const int l16 = lane & 15;
    const int b_r = l16 & 7;
    const int b_c = (l16 >> 3) * 16;
    const uint32_t b_off = (uint32_t)(nw * 32 + b_r) * ROWB + b_c;

    for (int s = 0; s < NST; s++) {
        asm volatile("cp.async.wait_group 1;" ::: "memory");
        __syncthreads();
        if (s + 2 < NST) issue(s + 2);
        else asm volatile("cp.async.commit_group;" ::: "memory");

        const uint32_t Ab = sb + (s % 3) * STAGE + AOFF;
        const uint32_t Bb = sb + (s % 3) * STAGE + BOFF;

#pragma unroll
        for (int ks = 0; ks < 4; ks++) {          // 4 x K=16 per 128B row
            uint32_t af[4][4];
#pragma unroll
            for (int mt = 0; mt < 4; mt++) {
                LDSM_X4(af[mt][0], af[mt][1], af[mt][2], af[mt][3],
                        Ab + a_off + mt * (16 * ROWB) + ks * 32);
            }
            uint32_t bf_[4][2];
#pragma unroll
            for (int nt = 0; nt < 4; nt++) {
                LDSM_X2(bf_[nt][0], bf_[nt][1],
                        Bb + b_off + nt * (8 * ROWB) + ks * 32);
            }
#pragma unroll
            for (int mt = 0; mt < 4; mt++)
#pragma unroll
                for (int nt = 0; nt < 4; nt++)
                    MMA16816(acc[mt][nt], af[mt], bf_[nt]);
        }
    }
    __syncthreads();   // pipeline buffers now dead; reuse smem for epilogue

    float* redv  = (float*)(smem);            // 4*128 floats = 2048 B
    float* redv2 = (float*)(smem + 2048);
    int*   redi  = (int*)  (smem + 4096);
    int*   redi2 = (int*)  (smem + 6144);

#pragma unroll
    for (int mt = 0; mt < 4; mt++) {
#pragma unroll
        for (int h = 0; h < 2; h++) {
            float v1 = -1e30f, v2 = -1e30f;
            int   i1 = 0,      i2 = 0;
#pragma unroll
            for (int nt = 0; nt < 4; nt++) {
#pragma unroll
                for (int c = 0; c < 2; c++) {
                    float v = acc[mt][nt][h * 2 + c];
                    int gc = n0 + nw * 32 + nt * 8 + (lane & 3) * 2 + c;
                    if (v > v1)      { v2 = v1; i2 = i1; v1 = v; i1 = gc; }
                    else if (v > v2) { v2 = v; i2 = gc; }
                }
            }
#pragma unroll
            for (int o = 1; o < 4; o <<= 1) {
                float ov1 = __shfl_xor_sync(0xffffffffu, v1, o);
                int   oi1 = __shfl_xor_sync(0xffffffffu, i1, o);
                float ov2 = __shfl_xor_sync(0xffffffffu, v2, o);
                int   oi2 = __shfl_xor_sync(0xffffffffu, i2, o);
                if (ov1 > v1 || (ov1 == v1 && oi1 < i1)) {
                    if (v1 > ov2) { v2 = v1; i2 = i1; }
                    else          { v2 = ov2; i2 = oi2; }
                    v1 = ov1; i1 = oi1;
                } else if (ov1 > v2) {
                    v2 = ov1; i2 = oi1;
                }
            }
            if ((lane & 3) == 0) {
                int rl = mw * 64 + mt * 16 + h * 8 + (lane >> 2);
                redv [nw * BM + rl] = v1;
                redv2[nw * BM + rl] = v2;
                redi [nw * BM + rl] = i1;
                redi2[nw * BM + rl] = i2;
            }
        }
    }
    __syncthreads();

    if (tid < BM) {
        float v1 = redv[tid], v2 = redv2[tid];
        int   i1 = redi[tid], i2 = redi2[tid];
#pragma unroll
        for (int w = 1; w < 4; w++) {
            float pv1 = redv[w * BM + tid], pv2 = redv2[w * BM + tid];
            int   pi1 = redi[w * BM + tid], pi2 = redi2[w * BM + tid];
            if (pv1 > v1 || (pv1 == v1 && pi1 < i1)) {
                if (v1 > pv2) { v2 = v1; i2 = i1; }
                else          { v2 = pv2; i2 = pi2; }
                v1 = pv1; i1 = pi1;
            } else if (pv1 > v2) {
                v2 = pv1; i2 = pi1;
            }
        }
        g_pm [blockIdx.x * NROW + r0 + tid] = v1;
        g_pm2[blockIdx.x * NROW + r0 + tid] = v2;
        g_pi [blockIdx.x * NROW + r0 + tid] = i1;
        g_pi2[blockIdx.x * NROW + r0 + tid] = i2;
    }
}

// ---------------------------------------------------------------------------
// Kernel 3: fold N-tile partials per row; build fix list (gap < TAU)
// ---------------------------------------------------------------------------
__global__ void reduce_fixlist_kernel() {
    int r = blockIdx.x * 256 + threadIdx.x;
    float v1 = g_pm[r], v2 = g_pm2[r];
    int   i1 = g_pi[r];
    for (int nt = 1; nt < NTILES_N; nt++) {
        float pv1 = g_pm[nt * NROW + r], pv2 = g_pm2[nt * NROW + r];
        int   pi1 = g_pi[nt * NROW + r];
        if (pv1 > v1 || (pv1 == v1 && pi1 < i1)) {
            v2 = fmaxf(v1, pv2); v1 = pv1; i1 = pi1;
        } else {
            v2 = fmaxf(v2, pv1);
        }
    }
    g_ridx[r] = i1;
    g_rv1[r]  = v1;
    if (v1 - v2 < TAU) {
        int p = atomicAdd(&g_nfix, 1);
        g_fixrows[p] = r;
    }
}

// ---------------------------------------------------------------------------
// Kernel 4: candidate-set exact rescoring (per-tile top-2 screen, exact fp32
// dot per candidate, first-max tie rules). Inactive blocks exit.
// ---------------------------------------------------------------------------
__global__ void __launch_bounds__(256) candexact_kernel() {
    const int fi = blockIdx.x;
    if (fi >= g_nfix) return;
    const int r = g_fixrows[fi];
    const int t = threadIdx.x;

    __shared__ int   cand[128];
    __shared__ int   ncand;
    __shared__ float red[8];
    __shared__ float bestv_s;
    __shared__ int   besti_s;

    if (t == 0) { ncand = 0; bestv_s = -1e30f; besti_s = 0x7FFFFFFF; }
    __syncthreads();

    const float thresh = g_rv1[r] - TAU2;
    if (t < 2 * NTILES_N) {               // 128 screen entries
        int tile  = t >> 1;
        int which = t & 1;
        float v = which ? g_pm2[tile * NROW + r] : g_pm[tile * NROW + r];
        int   i = which ? g_pi2[tile * NROW + r] : g_pi[tile * NROW + r];
        if (v >= thresh) {
            int p = atomicAdd(&ncand, 1);
            cand[p] = i;
        }
    }
    __syncthreads();

    float4 x4 = *(const float4*)&g_Xn[(long long)r * F_ + t * 4];

    const int nc = ncand;
    for (int c = 0; c < nc; c++) {
        int idx = cand[c];
        float4 y4 = *(const float4*)&g_Yn[(long long)idx * F_ + t * 4];
        float s = x4.x * y4.x + x4.y * y4.y + x4.z * y4.z + x4.w * y4.w;
#pragma unroll
        for (int o = 16; o > 0; o >>= 1) s += __shfl_xor_sync(0xffffffffu, s, o);
        if ((t & 31) == 0) red[t >> 5] = s;
        __syncthreads();
        if (t == 0) {
            float z = 0.0f;
#pragma unroll
            for (int w = 0; w < 8; w++) z += red[w];
            if (z > bestv_s || (z == bestv_s && idx < besti_s)) {
                bestv_s = z; besti_s = idx;
            }
        }
        __syncthreads();
    }

    if (t == 0) g_ridx[r] = besti_s;
}

// ---------------------------------------------------------------------------
// Kernel 5: finalize + gather fused — exact fp32 rescore of chosen idx
// (feeds cosloss) AND write new_x (scalar stores: out may be 4B-aligned).
// ---------------------------------------------------------------------------
__global__ void finalize_gather_kernel(float* __restrict__ newx) {
    const int r = blockIdx.x;
    const int t = threadIdx.x;
    const int idx = g_ridx[r];

    const int b  = r >> 10;
    const int wb = (r >> 5) & 31;
    const int hb = r & 31;

    const int f0 = t * 4;
    const int a  = f0 >> 8;
    const int c  = (f0 >> 6) & 3;
    const int d  = f0 & 63;

    float4 x4 = *(const float4*)&g_Xn[(long long)r   * F_ + f0];
    float4 y4 = *(const float4*)&g_Yn[(long long)idx * F_ + f0];

    long long off = ((long long)(b * W_ + wb * BS_ + a) * H_ + hb * BS_ + c) * D_ + d;
    newx[off + 0] = y4.x;
    newx[off + 1] = y4.y;
    newx[off + 2] = y4.z;
    newx[off + 3] = y4.w;

    float s = x4.x * y4.x + x4.y * y4.y + x4.z * y4.z + x4.w * y4.w;
#pragma unroll
    for (int o = 16; o > 0; o >>= 1) s += __shfl_xor_sync(0xffffffffu, s, o);
    __shared__ float red[8];
    if ((t & 31) == 0) red[t >> 5] = s;
    __syncthreads();
    if (t == 0) {
        float z = 0.0f;
#pragma unroll
        for (int w = 0; w < 8; w++) z += red[w];
        g_rmax[r] = z;
    }
}

// ---------------------------------------------------------------------------
// Kernel 6: cosloss = mean(1 - rowmax)
// ---------------------------------------------------------------------------
__global__ void cosloss_kernel(float* __restrict__ out_scalar) {
    const int t = threadIdx.x;
    float s = 0.0f;
    for (int r = t; r < NROW; r += 1024) s += 1.0f - g_rmax[r];
#pragma unroll
    for (int o = 16; o > 0; o >>= 1) s += __shfl_xor_sync(0xffffffffu, s, o);
    __shared__ float red[32];
    if ((t & 31) == 0) red[t >> 5] = s;
    __syncthreads();
    if (t < 32) {
        float z = red[t];
#pragma unroll
        for (int o = 16; o > 0; o >>= 1) z += __shfl_xor_sync(0xffffffffu, z, o);
        if (t == 0) *out_scalar = z * (1.0f / NROW);
    }
}

// ---------------------------------------------------------------------------
extern "C" void kernel_launch(void* const* d_in, const int* in_sizes, int n_in,
                              void* d_out, int out_size) {
    const float* x = (const float*)d_in[0];
    const float* y = (const float*)d_in[1];
    float* out = (float*)d_out;

    float* newx = out;
    if ((long long)out_size > NX_ELEMS) {
        newx = out + ((long long)out_size - NX_ELEMS);
    }

    static bool attr_set = false;
    if (!attr_set) {
        cudaFuncSetAttribute(gemm_argmax_mma,
                             cudaFuncAttributeMaxDynamicSharedMemorySize, SMEM_TOTAL);
        attr_set = true;
    }

    norm_combine_kernel<<<2 * NROW, 256>>>(x, y);

    dim3 ggrid(NTILES_N, NTILES_M);
    gemm_argmax_mma<<<ggrid, 256, SMEM_TOTAL>>>();

    reduce_fixlist_kernel<<<NROW / 256, 256>>>();

    candexact_kernel<<<NROW, 256>>>();

    finalize_gather_kernel<<<NROW, 256>>>(newx);

    if ((long long)out_size > NX_ELEMS) {
        cosloss_kernel<<<1, 1024>>>(out);
    }
}

// round 17
// speedup vs baseline: 1.1289x; 1.0216x over previous
#include <cuda_runtime.h>
#include <cuda_bf16.h>
#include <cstdint>
#include <math.h>

// Problem constants (fixed by setup_inputs): x,y [8,128,128,64] f32, blocksize 4
constexpr int B_   = 8;
constexpr int W_   = 128;
constexpr int H_   = 128;
constexpr int D_   = 64;
constexpr int BS_  = 4;
constexpr int F_   = 1024;
constexpr int NROW = 8192;
constexpr long long NX_ELEMS = (long long)B_ * W_ * H_ * D_; // 8388608

// bf16 GEMM tiling (R13 verified optimum): 128x128 CTA tile, 8 warps
// (2M x 4N), 64x32 per warp, BK=64 (128B rows), 16 stages, ldmatrix,
// 2 CTAs/SM (16 warps/SM = register-file cap at ~126 regs).
constexpr int BM = 128;
constexpr int BN = 128;
constexpr int BK = 64;
constexpr int NTILES_N = NROW / BN;     // 64
constexpr int NTILES_M = NROW / BM;     // 64
constexpr int NST = F_ / BK;            // 16 stages

constexpr int ROWB = 144;               // 128B data + 16B pad (conflict-free)
constexpr int AOFF = 0;
constexpr int BOFF = BM * ROWB;
constexpr int STAGE = (BM + BN) * ROWB;            // 36864
constexpr int SMEM_TOTAL = 3 * STAGE;              // 110592 -> 2 CTAs/SM

// bf16 coarse gap-error sigma ~1.4e-4 (validated R9/R10).
constexpr float TAU  = 5e-4f;   // fix-row trigger
constexpr float TAU2 = 1e-3f;   // candidate screen (~7 sigma)

// Scratch (__device__ globals; allocation-free rule)
__device__ __nv_bfloat16 g_Xh[NROW * F_];
__device__ __nv_bfloat16 g_Yh[NROW * F_];
__device__ float g_Xn[NROW * F_];
__device__ float g_Yn[NROW * F_];
__device__ float g_pm [NTILES_N * NROW];
__device__ float g_pm2[NTILES_N * NROW];
__device__ int   g_pi [NTILES_N * NROW];
__device__ int   g_pi2[NTILES_N * NROW];
__device__ float g_rmax[NROW];
__device__ float g_rv1[NROW];
__device__ int   g_ridx[NROW];
__device__ int   g_fixrows[NROW];
__device__ int   g_nfix;

// ---------------------------------------------------------------------------
// helpers
// ---------------------------------------------------------------------------
__device__ __forceinline__ uint32_t smem_u32(const void* p) {
    uint32_t a;
    asm("{ .reg .u64 t; cvta.to.shared.u64 t, %1; cvt.u32.u64 %0, t; }"
        : "=r"(a) : "l"(p));
    return a;
}

#define CP16(dst, src) \
    asm volatile("cp.async.cg.shared.global [%0], [%1], 16;" \
                 :: "r"(dst), "l"(src) : "memory")

#define LDSM_X4(r0, r1, r2, r3, addr) \
    asm volatile("ldmatrix.sync.aligned.m8n8.x4.shared.b16 {%0,%1,%2,%3}, [%4];" \
        : "=r"(r0), "=r"(r1), "=r"(r2), "=r"(r3) : "r"(addr))

#define MMA16816(d, a, b) \
    asm volatile("mma.sync.aligned.m16n8k16.row.col.f32.bf16.bf16.f32 " \
        "{%0,%1,%2,%3}, {%4,%5,%6,%7}, {%8,%9}, {%0,%1,%2,%3};" \
        : "+f"((d)[0]), "+f"((d)[1]), "+f"((d)[2]), "+f"((d)[3]) \
        : "r"((a)[0]), "r"((a)[1]), "r"((a)[2]), "r"((a)[3]), \
          "r"((b)[0]), "r"((b)[1]))

// ---------------------------------------------------------------------------
// Kernel 1: combine + normalize; writes bf16 hi + fp32. Resets g_nfix.
// ---------------------------------------------------------------------------
__global__ void norm_combine_kernel(const float* __restrict__ x,
                                    const float* __restrict__ y) {
    if (blockIdx.x == 0 && threadIdx.x == 0) g_nfix = 0;

    int r = blockIdx.x;
    const float* src;
    bool isx;
    if (r < NROW) { src = x; isx = true; }
    else          { r -= NROW; src = y; isx = false; }

    const int b  = r >> 10;
    const int wb = (r >> 5) & 31;
    const int hb = r & 31;
    const int t  = threadIdx.x;

    float v[4];
#pragma unroll
    for (int j = 0; j < 4; j++) {
        int f = t + j * 256;
        int a = f >> 8;
        int c = (f >> 6) & 3;
        int d = f & 63;
        v[j] = src[((b * W_ + wb * BS_ + a) * H_ + hb * BS_ + c) * D_ + d];
    }

    __shared__ float red[8];
    __shared__ float bcast;

    float s = v[0] + v[1] + v[2] + v[3];
#pragma unroll
    for (int o = 16; o > 0; o >>= 1) s += __shfl_xor_sync(0xffffffffu, s, o);
    if ((t & 31) == 0) red[t >> 5] = s;
    __syncthreads();
    if (t < 32) {
        float z = (t < 8) ? red[t] : 0.0f;
#pragma unroll
        for (int o = 4; o > 0; o >>= 1) z += __shfl_xor_sync(0xffffffffu, z, o);
        if (t == 0) bcast = z;
    }
    __syncthreads();
    const float mean = bcast * (1.0f / F_);
    __syncthreads();

    float q = 0.0f;
#pragma unroll
    for (int j = 0; j < 4; j++) { float u = v[j] - mean; q += u * u; }
#pragma unroll
    for (int o = 16; o > 0; o >>= 1) q += __shfl_xor_sync(0xffffffffu, q, o);
    if ((t & 31) == 0) red[t >> 5] = q;
    __syncthreads();
    if (t < 32) {
        float z = (t < 8) ? red[t] : 0.0f;
#pragma unroll
        for (int o = 4; o > 0; o >>= 1) z += __shfl_xor_sync(0xffffffffu, z, o);
        if (t == 0) bcast = z;
    }
    __syncthreads();
    const float scale = 1.0f / (sqrtf(bcast) + 1e-5f);

    long long base = (long long)r * F_;
#pragma unroll
    for (int j = 0; j < 4; j++) {
        float w = (v[j] - mean) * scale;
        long long o = base + t + j * 256;
        if (isx) { g_Xh[o] = __float2bfloat16(w); g_Xn[o] = w; }
        else     { g_Yh[o] = __float2bfloat16(w); g_Yn[o] = w; }
    }
}

// ---------------------------------------------------------------------------
// Kernel 2: coarse bf16 GEMM (R13 config + paired-B ldmatrix.x4: 6 shared
// ops per ks instead of 8). Fused per-row top-2 + indices.
// ---------------------------------------------------------------------------
__global__ void __launch_bounds__(256, 2) gemm_argmax_mma() {
    extern __shared__ __align__(128) char smem[];
    const uint32_t sb = smem_u32(smem);

    const int tid  = threadIdx.x;
    const int wid  = tid >> 5;
    const int lane = tid & 31;
    const int mw   = wid >> 2;
    const int nw   = wid & 3;
    const int n0   = blockIdx.x * BN;
    const int r0   = blockIdx.y * BM;

    float acc[4][4][4];
#pragma unroll
    for (int mt = 0; mt < 4; mt++)
#pragma unroll
        for (int nt = 0; nt < 4; nt++)
#pragma unroll
            for (int k = 0; k < 4; k++) acc[mt][nt][k] = 0.0f;

    auto issue = [&](int s) {
        const int k0 = s * BK;
        const uint32_t base = sb + (s % 3) * STAGE;
#pragma unroll
        for (int j = 0; j < 4; j++) {             // A: 128 rows x 8 x 16B
            int idx = tid + j * 256;
            int m = idx >> 3, ch = idx & 7;
            CP16(base + AOFF + m * ROWB + ch * 16,
                 g_Xh + (long long)(r0 + m) * F_ + k0 + ch * 8);
        }
#pragma unroll
        for (int j = 0; j < 4; j++) {             // B: 128 rows x 8 x 16B
            int idx = tid + j * 256;
            int n = idx >> 3, ch = idx & 7;
            CP16(base + BOFF + n * ROWB + ch * 16,
                 g_Yh + (long long)(n0 + n) * F_ + k0 + ch * 8);
        }
        asm volatile("cp.async.commit_group;" ::: "memory");
    };

    issue(0); issue(1);

    // ldmatrix per-lane source offsets.
    // A x4 (16x16): mat0 rows0-7 b0-15, mat1 rows8-15 b0-15,
    //               mat2 rows0-7 b16-31, mat3 rows8-15 b16-31.
    const int a_r = (lane & 7) + ((lane >> 3) & 1) * 8;
    const int a_c = (lane >> 4) * 16;
    const uint32_t a_off = (uint32_t)(mw * 64 + a_r) * ROWB + a_c;
    // B x4 pairs two 8-row nt-blocks:
    //   group0 (lanes 0-7):  rows p*16+0..7,  bytes 0-15  -> r0 = bf[2p][0]
    //   group1 (lanes 8-15): rows p*16+0..7,  bytes 16-31 -> r1 = bf[2p][1]
    //   group2 (lanes16-23): rows p*16+8..15, bytes 0-15  -> r2 = bf[2p+1][0]
    //   group3 (lanes24-31): rows p*16+8..15, bytes 16-31 -> r3 = bf[2p+1][1]
    const int bg  = lane >> 3;                  // 0..3
    const int b_r = (lane & 7) + (bg >> 1) * 8;
    const int b_c = (bg & 1) * 16;
    const uint32_t b_off = (uint32_t)(nw * 32 + b_r) * ROWB + b_c;

    for (int s = 0; s < NST; s++) {
        asm volatile("cp.async.wait_group 1;" ::: "memory");
        __syncthreads();
        if (s + 2 < NST) issue(s + 2);
        else asm volatile("cp.async.commit_group;" ::: "memory");

        const uint32_t Ab = sb + (s % 3) * STAGE + AOFF;
        const uint32_t Bb = sb + (s % 3) * STAGE + BOFF;

#pragma unroll
        for (int ks = 0; ks < 4; ks++) {          // 4 x K=16 per 128B row
            uint32_t af[4][4];
#pragma unroll
            for (int mt = 0; mt < 4; mt++) {
                LDSM_X4(af[mt][0], af[mt][1], af[mt][2], af[mt][3],
                        Ab + a_off + mt * (16 * ROWB) + ks * 32);
            }
            uint32_t bf_[4][2];
#pragma unroll
            for (int p = 0; p < 2; p++) {         // 2 x4 loads cover nt 0..3
                LDSM_X4(bf_[2*p][0], bf_[2*p][1], bf_[2*p+1][0], bf_[2*p+1][1],
                        Bb + b_off + p * (16 * ROWB) + ks * 32);
            }
#pragma unroll
            for (int mt = 0; mt < 4; mt++)
#pragma unroll
                for (int nt = 0; nt < 4; nt++)
                    MMA16816(acc[mt][nt], af[mt], bf_[nt]);
        }
    }
    __syncthreads();   // pipeline buffers now dead; reuse smem for epilogue

    float* redv  = (float*)(smem);            // 4*128 floats = 2048 B
    float* redv2 = (float*)(smem + 2048);
    int*   redi  = (int*)  (smem + 4096);
    int*   redi2 = (int*)  (smem + 6144);

#pragma unroll
    for (int mt = 0; mt < 4; mt++) {
#pragma unroll
        for (int h = 0; h < 2; h++) {
            float v1 = -1e30f, v2 = -1e30f;
            int   i1 = 0,      i2 = 0;
#pragma unroll
            for (int nt = 0; nt < 4; nt++) {
#pragma unroll
                for (int c = 0; c < 2; c++) {
                    float v = acc[mt][nt][h * 2 + c];
                    int gc = n0 + nw * 32 + nt * 8 + (lane & 3) * 2 + c;
                    if (v > v1)      { v2 = v1; i2 = i1; v1 = v; i1 = gc; }
                    else if (v > v2) { v2 = v; i2 = gc; }
                }
            }
#pragma unroll
            for (int o = 1; o < 4; o <<= 1) {
                float ov1 = __shfl_xor_sync(0xffffffffu, v1, o);
                int   oi1 = __shfl_xor_sync(0xffffffffu, i1, o);
                float ov2 = __shfl_xor_sync(0xffffffffu, v2, o);
                int   oi2 = __shfl_xor_sync(0xffffffffu, i2, o);
                if (ov1 > v1 || (ov1 == v1 && oi1 < i1)) {
                    if (v1 > ov2) { v2 = v1; i2 = i1; }
                    else          { v2 = ov2; i2 = oi2; }
                    v1 = ov1; i1 = oi1;
                } else if (ov1 > v2) {
                    v2 = ov1; i2 = oi1;
                }
            }
            if ((lane & 3) == 0) {
                int rl = mw * 64 + mt * 16 + h * 8 + (lane >> 2);
                redv [nw * BM + rl] = v1;
                redv2[nw * BM + rl] = v2;
                redi [nw * BM + rl] = i1;
                redi2[nw * BM + rl] = i2;
            }
        }
    }
    __syncthreads();

    if (tid < BM) {
        float v1 = redv[tid], v2 = redv2[tid];
        int   i1 = redi[tid], i2 = redi2[tid];
#pragma unroll
        for (int w = 1; w < 4; w++) {
            float pv1 = redv[w * BM + tid], pv2 = redv2[w * BM + tid];
            int   pi1 = redi[w * BM + tid], pi2 = redi2[w * BM + tid];
            if (pv1 > v1 || (pv1 == v1 && pi1 < i1)) {
                if (v1 > pv2) { v2 = v1; i2 = i1; }
                else          { v2 = pv2; i2 = pi2; }
                v1 = pv1; i1 = pi1;
            } else if (pv1 > v2) {
                v2 = pv1; i2 = pi1;
            }
        }
        g_pm [blockIdx.x * NROW + r0 + tid] = v1;
        g_pm2[blockIdx.x * NROW + r0 + tid] = v2;
        g_pi [blockIdx.x * NROW + r0 + tid] = i1;
        g_pi2[blockIdx.x * NROW + r0 + tid] = i2;
    }
}

// ---------------------------------------------------------------------------
// Kernel 3: fold N-tile partials per row; build fix list (gap < TAU)
// ---------------------------------------------------------------------------
__global__ void reduce_fixlist_kernel() {
    int r = blockIdx.x * 256 + threadIdx.x;
    float v1 = g_pm[r], v2 = g_pm2[r];
    int   i1 = g_pi[r];
    for (int nt = 1; nt < NTILES_N; nt++) {
        float pv1 = g_pm[nt * NROW + r], pv2 = g_pm2[nt * NROW + r];
        int   pi1 = g_pi[nt * NROW + r];
        if (pv1 > v1 || (pv1 == v1 && pi1 < i1)) {
            v2 = fmaxf(v1, pv2); v1 = pv1; i1 = pi1;
        } else {
            v2 = fmaxf(v2, pv1);
        }
    }
    g_ridx[r] = i1;
    g_rv1[r]  = v1;
    if (v1 - v2 < TAU) {
        int p = atomicAdd(&g_nfix, 1);
        g_fixrows[p] = r;
    }
}

// ---------------------------------------------------------------------------
// Kernel 4: candidate-set exact rescoring (per-tile top-2 screen, exact fp32
// dot per candidate, first-max tie rules). Inactive blocks exit.
// ---------------------------------------------------------------------------
__global__ void __launch_bounds__(256) candexact_kernel() {
    const int fi = blockIdx.x;
    if (fi >= g_nfix) return;
    const int r = g_fixrows[fi];
    const int t = threadIdx.x;

    __shared__ int   cand[128];
    __shared__ int   ncand;
    __shared__ float red[8];
    __shared__ float bestv_s;
    __shared__ int   besti_s;

    if (t == 0) { ncand = 0; bestv_s = -1e30f; besti_s = 0x7FFFFFFF; }
    __syncthreads();

    const float thresh = g_rv1[r] - TAU2;
    if (t < 2 * NTILES_N) {               // 128 screen entries
        int tile  = t >> 1;
        int which = t & 1;
        float v = which ? g_pm2[tile * NROW + r] : g_pm[tile * NROW + r];
        int   i = which ? g_pi2[tile * NROW + r] : g_pi[tile * NROW + r];
        if (v >= thresh) {
            int p = atomicAdd(&ncand, 1);
            cand[p] = i;
        }
    }
    __syncthreads();

    float4 x4 = *(const float4*)&g_Xn[(long long)r * F_ + t * 4];

    const int nc = ncand;
    for (int c = 0; c < nc; c++) {
        int idx = cand[c];
        float4 y4 = *(const float4*)&g_Yn[(long long)idx * F_ + t * 4];
        float s = x4.x * y4.x + x4.y * y4.y + x4.z * y4.z + x4.w * y4.w;
#pragma unroll
        for (int o = 16; o > 0; o >>= 1) s += __shfl_xor_sync(0xffffffffu, s, o);
        if ((t & 31) == 0) red[t >> 5] = s;
        __syncthreads();
        if (t == 0) {
            float z = 0.0f;
#pragma unroll
            for (int w = 0; w < 8; w++) z += red[w];
            if (z > bestv_s || (z == bestv_s && idx < besti_s)) {
                bestv_s = z; besti_s = idx;
            }
        }
        __syncthreads();
    }

    if (t == 0) g_ridx[r] = besti_s;
}

// ---------------------------------------------------------------------------
// Kernel 5: finalize + gather fused — exact fp32 rescore of chosen idx
// (feeds cosloss) AND write new_x (scalar stores: out may be 4B-aligned).
// ---------------------------------------------------------------------------
__global__ void finalize_gather_kernel(float* __restrict__ newx) {
    const int r = blockIdx.x;
    const int t = threadIdx.x;
    const int idx = g_ridx[r];

    const int b  = r >> 10;
    const int wb = (r >> 5) & 31;
    const int hb = r & 31;

    const int f0 = t * 4;
    const int a  = f0 >> 8;
    const int c  = (f0 >> 6) & 3;
    const int d  = f0 & 63;

    float4 x4 = *(const float4*)&g_Xn[(long long)r   * F_ + f0];
    float4 y4 = *(const float4*)&g_Yn[(long long)idx * F_ + f0];

    long long off = ((long long)(b * W_ + wb * BS_ + a) * H_ + hb * BS_ + c) * D_ + d;
    newx[off + 0] = y4.x;
    newx[off + 1] = y4.y;
    newx[off + 2] = y4.z;
    newx[off + 3] = y4.w;

    float s = x4.x * y4.x + x4.y * y4.y + x4.z * y4.z + x4.w * y4.w;
#pragma unroll
    for (int o = 16; o > 0; o >>= 1) s += __shfl_xor_sync(0xffffffffu, s, o);
    __shared__ float red[8];
    if ((t & 31) == 0) red[t >> 5] = s;
    __syncthreads();
    if (t == 0) {
        float z = 0.0f;
#pragma unroll
        for (int w = 0; w < 8; w++) z += red[w];
        g_rmax[r] = z;
    }
}

// ---------------------------------------------------------------------------
// Kernel 6: cosloss = mean(1 - rowmax)
// ---------------------------------------------------------------------------
__global__ void cosloss_kernel(float* __restrict__ out_scalar) {
    const int t = threadIdx.x;
    float s = 0.0f;
    for (int r = t; r < NROW; r += 1024) s += 1.0f - g_rmax[r];
#pragma unroll
    for (int o = 16; o > 0; o >>= 1) s += __shfl_xor_sync(0xffffffffu, s, o);
    __shared__ float red[32];
    if ((t & 31) == 0) red[t >> 5] = s;
    __syncthreads();
    if (t < 32) {
        float z = red[t];
#pragma unroll
        for (int o = 16; o > 0; o >>= 1) z += __shfl_xor_sync(0xffffffffu, z, o);
        if (t == 0) *out_scalar = z * (1.0f / NROW);
    }
}

// ---------------------------------------------------------------------------
extern "C" void kernel_launch(void* const* d_in, const int* in_sizes, int n_in,
                              void* d_out, int out_size) {
    const float* x = (const float*)d_in[0];
    const float* y = (const float*)d_in[1];
    float* out = (float*)d_out;

    float* newx = out;
    if ((long long)out_size > NX_ELEMS) {
        newx = out + ((long long)out_size - NX_ELEMS);
    }

    static bool attr_set = false;
    if (!attr_set) {
        cudaFuncSetAttribute(gemm_argmax_mma,
                             cudaFuncAttributeMaxDynamicSharedMemorySize, SMEM_TOTAL);
        attr_set = true;
    }

    norm_combine_kernel<<<2 * NROW, 256>>>(x, y);

    dim3 ggrid(NTILES_N, NTILES_M);
    gemm_argmax_mma<<<ggrid, 256, SMEM_TOTAL>>>();

    reduce_fixlist_kernel<<<NROW / 256, 256>>>();

    candexact_kernel<<<NROW, 256>>>();

    finalize_gather_kernel<<<NROW, 256>>>(newx);

    if ((long long)out_size > NX_ELEMS) {
        cosloss_kernel<<<1, 1024>>>(out);
    }
}